// round 7
// baseline (speedup 1.0000x reference)
#include <cuda_runtime.h>
#include <cuda_bf16.h>
#include <cstdint>
#include <cstddef>

#define SEQ    4096
#define DMODEL 512
#define NHEAD  8
#define DK     64

// ---------------------------------------------------------------------------
// Scratch (device globals — no allocation in kernel_launch)
// ---------------------------------------------------------------------------
__device__ __nv_bfloat16 g_qin_h[2 * SEQ * DMODEL], g_qin_l[2 * SEQ * DMODEL];
__device__ __nv_bfloat16 g_kin_h[2 * SEQ * DMODEL], g_kin_l[2 * SEQ * DMODEL];
__device__ __nv_bfloat16 g_vin_h[2 * SEQ * DMODEL], g_vin_l[2 * SEQ * DMODEL];
__device__ __nv_bfloat16 g_Qhi[2 * SEQ * DMODEL], g_Qlo[2 * SEQ * DMODEL];
__device__ __nv_bfloat16 g_Khi[2 * SEQ * DMODEL], g_Klo[2 * SEQ * DMODEL];
__device__ __nv_bfloat16 g_Vhi[2 * SEQ * DMODEL], g_Vlo[2 * SEQ * DMODEL];
__device__ __nv_bfloat16 g_Chi[2 * SEQ * DMODEL], g_Clo[2 * SEQ * DMODEL];
__device__ __nv_bfloat16 g_Wq_h[DMODEL * DMODEL], g_Wq_l[DMODEL * DMODEL];
__device__ __nv_bfloat16 g_Wk_h[DMODEL * DMODEL], g_Wk_l[DMODEL * DMODEL];
__device__ __nv_bfloat16 g_Wv_h[DMODEL * DMODEL], g_Wv_l[DMODEL * DMODEL];
__device__ __nv_bfloat16 g_Wo_h[DMODEL * DMODEL], g_Wo_l[DMODEL * DMODEL];

// ---------------------------------------------------------------------------
// helpers
// ---------------------------------------------------------------------------
#define SWZ(o) ((o) ^ (((o) >> 3) & 0x70))

__device__ __forceinline__ uint32_t smem_u32(const void* p) {
    uint32_t a;
    asm("{ .reg .u64 t; cvta.to.shared.u64 t, %1; cvt.u32.u64 %0, t; }" : "=r"(a) : "l"(p));
    return a;
}
__device__ __forceinline__ void cpa16(uint32_t dst, const void* src) {
    asm volatile("cp.async.cg.shared.global [%0], [%1], 16;" :: "r"(dst), "l"(src) : "memory");
}
#define CP_COMMIT() asm volatile("cp.async.commit_group;" ::: "memory")
#define CP_WAIT(n)  asm volatile("cp.async.wait_group %0;" :: "n"(n) : "memory")

__device__ __forceinline__ void ldsm_x4(uint32_t* r, uint32_t addr) {
    asm volatile("ldmatrix.sync.aligned.m8n8.x4.shared.b16 {%0,%1,%2,%3}, [%4];"
                 : "=r"(r[0]), "=r"(r[1]), "=r"(r[2]), "=r"(r[3]) : "r"(addr));
}
__device__ __forceinline__ void ldsm_x4t(uint32_t* r, uint32_t addr) {
    asm volatile("ldmatrix.sync.aligned.m8n8.x4.trans.shared.b16 {%0,%1,%2,%3}, [%4];"
                 : "=r"(r[0]), "=r"(r[1]), "=r"(r[2]), "=r"(r[3]) : "r"(addr));
}
__device__ __forceinline__ void ldsm_x2(uint32_t& r0, uint32_t& r1, uint32_t addr) {
    asm volatile("ldmatrix.sync.aligned.m8n8.x2.shared.b16 {%0,%1}, [%2];"
                 : "=r"(r0), "=r"(r1) : "r"(addr));
}
__device__ __forceinline__ void mma16816(float* c, const uint32_t* a, uint32_t b0, uint32_t b1) {
    asm volatile("mma.sync.aligned.m16n8k16.row.col.f32.bf16.bf16.f32 "
                 "{%0,%1,%2,%3}, {%4,%5,%6,%7}, {%8,%9}, {%0,%1,%2,%3};"
                 : "+f"(c[0]), "+f"(c[1]), "+f"(c[2]), "+f"(c[3])
                 : "r"(a[0]), "r"(a[1]), "r"(a[2]), "r"(a[3]), "r"(b0), "r"(b1));
}
__device__ __forceinline__ void split2(float a, float b, uint32_t& hi, uint32_t& lo) {
    __nv_bfloat162 hp = __floats2bfloat162_rn(a, b);
    float ar = a - __bfloat162float(hp.x);
    float br = b - __bfloat162float(hp.y);
    __nv_bfloat162 lp = __floats2bfloat162_rn(ar, br);
    hi = *reinterpret_cast<uint32_t*>(&hp);
    lo = *reinterpret_cast<uint32_t*>(&lp);
}

// ---------------------------------------------------------------------------
// batched elementwise fp32 -> bf16 hi/lo (grid.z selects tensor)
// ---------------------------------------------------------------------------
struct Conv4Args {
    const float* X[4];
    __nv_bfloat16* hi[4];
    __nv_bfloat16* lo[4];
};

__global__ __launch_bounds__(256)
void convert_split4(Conv4Args args, int n4)
{
    const int g = blockIdx.z;
    int i = blockIdx.x * blockDim.x + threadIdx.x;
    if (i >= n4) return;
    float4 v = *reinterpret_cast<const float4*>(args.X[g] + (size_t)i * 4);
    uint32_t h0, l0, h1, l1;
    split2(v.x, v.y, h0, l0);
    split2(v.z, v.w, h1, l1);
    *reinterpret_cast<uint2*>(args.hi[g] + (size_t)i * 4) = make_uint2(h0, h1);
    *reinterpret_cast<uint2*>(args.lo[g] + (size_t)i * 4) = make_uint2(l0, l1);
}

// ---------------------------------------------------------------------------
// Tensor-core GEMM core (128x128 tile, K-step 64, 8 warps, double-buffered)
// ---------------------------------------------------------------------------
#define GA_HI 0u
#define GA_LO 16384u
#define GW_HI 32768u
#define GW_LO 49152u
#define GBUF  65536u
#define GSMEM (131072u + 1024u)

struct Gemm3Args {
    const __nv_bfloat16* Ah[3];
    const __nv_bfloat16* Al[3];
    const __nv_bfloat16* Wh[3];
    const __nv_bfloat16* Wl[3];
    const float* bias[3];
    __nv_bfloat16* Ch[3];
    __nv_bfloat16* Cl[3];
};

template<bool SPLIT>
__device__ __forceinline__ void gemm_core(
    const __nv_bfloat16* __restrict__ Ahi, const __nv_bfloat16* __restrict__ Alo,
    const __nv_bfloat16* __restrict__ Whi, const __nv_bfloat16* __restrict__ Wlo,
    const float* __restrict__ bias, float* __restrict__ Cf,
    __nv_bfloat16* __restrict__ Chi, __nv_bfloat16* __restrict__ Clo,
    int M, int N, int K, char* sb, uint32_t sbase)
{
    const int tid  = threadIdx.x;
    const int wid  = tid >> 5;
    const int lane = tid & 31;
    const int wm   = wid & 1;
    const int wn   = wid >> 1;

    const int brow = blockIdx.y * 128;
    const int bcol = blockIdx.x * 128;

    const int row = tid >> 1;
    const int ch0 = (tid & 1) * 4;

    const __nv_bfloat16* a_h = Ahi + (size_t)(brow + row) * K;
    const __nv_bfloat16* a_l = Alo + (size_t)(brow + row) * K;
    const __nv_bfloat16* w_h = Whi + (size_t)(bcol + row) * K;
    const __nv_bfloat16* w_l = Wlo + (size_t)(bcol + row) * K;
    const uint32_t so_base = (uint32_t)row * 128u;

    {
#pragma unroll
        for (int e = 0; e < 4; e++) {
            int ch = ch0 + e;
            uint32_t so = SWZ(so_base + (uint32_t)ch * 16u);
            cpa16(sbase + GA_HI + so, a_h + ch * 8);
            cpa16(sbase + GA_LO + so, a_l + ch * 8);
            cpa16(sbase + GW_HI + so, w_h + ch * 8);
            cpa16(sbase + GW_LO + so, w_l + ch * 8);
        }
        CP_COMMIT();
    }

    float acc[4][4][4];
#pragma unroll
    for (int i = 0; i < 4; i++)
#pragma unroll
        for (int j = 0; j < 4; j++)
#pragma unroll
            for (int e = 0; e < 4; e++) acc[i][j][e] = 0.f;

    const int nKT = K / 64;
    for (int kt = 0; kt < nKT; kt++) {
        const uint32_t p  = (uint32_t)(kt & 1);
        const uint32_t bb = sbase + p * GBUF;

        if (kt + 1 < nKT) {
            const int k1 = (kt + 1) * 64;
            uint32_t ob = sbase + (p ^ 1u) * GBUF;
#pragma unroll
            for (int e = 0; e < 4; e++) {
                int ch = ch0 + e;
                uint32_t so = SWZ(so_base + (uint32_t)ch * 16u);
                cpa16(ob + GA_HI + so, a_h + k1 + ch * 8);
                cpa16(ob + GA_LO + so, a_l + k1 + ch * 8);
                cpa16(ob + GW_HI + so, w_h + k1 + ch * 8);
                cpa16(ob + GW_LO + so, w_l + k1 + ch * 8);
            }
        }
        CP_COMMIT();
        CP_WAIT(1);
        __syncthreads();

#pragma unroll
        for (int ks = 0; ks < 4; ks++) {
            uint32_t ah[4][4], al[4][4];
            const int cb = lane >> 4;
#pragma unroll
            for (int i = 0; i < 4; i++) {
                int r = wm * 64 + i * 16 + (lane & 15);
                uint32_t off = SWZ((uint32_t)r * 128u + (uint32_t)(ks * 2 + cb) * 16u);
                ldsm_x4(ah[i], bb + GA_HI + off);
                ldsm_x4(al[i], bb + GA_LO + off);
            }
            uint32_t bh[4][2], bl[4][2];
#pragma unroll
            for (int jp = 0; jp < 2; jp++) {
                // x4: lanes 0-15 -> block 2jp, lanes 16-31 -> block 2jp+1
                int wr = wn * 32 + (jp * 2 + (lane >> 4)) * 8 + (lane & 7);
                int ch = ks * 2 + ((lane >> 3) & 1);
                uint32_t off = SWZ((uint32_t)wr * 128u + (uint32_t)ch * 16u);
                uint32_t t4[4];
                ldsm_x4(t4, bb + GW_HI + off);
                bh[jp * 2][0] = t4[0]; bh[jp * 2][1] = t4[1];
                bh[jp * 2 + 1][0] = t4[2]; bh[jp * 2 + 1][1] = t4[3];
                ldsm_x4(t4, bb + GW_LO + off);
                bl[jp * 2][0] = t4[0]; bl[jp * 2][1] = t4[1];
                bl[jp * 2 + 1][0] = t4[2]; bl[jp * 2 + 1][1] = t4[3];
            }
#pragma unroll
            for (int i = 0; i < 4; i++)
#pragma unroll
                for (int j = 0; j < 4; j++) {
                    mma16816(acc[i][j], ah[i], bh[j][0], bh[j][1]);
                    mma16816(acc[i][j], al[i], bh[j][0], bh[j][1]);
                    mma16816(acc[i][j], ah[i], bl[j][0], bl[j][1]);
                }
        }
        __syncthreads();
    }

#pragma unroll
    for (int i = 0; i < 4; i++) {
        const int gr0 = brow + wm * 64 + i * 16 + (lane >> 2);
        const int gr1 = gr0 + 8;
#pragma unroll
        for (int j = 0; j < 4; j++) {
            const int gc = bcol + wn * 32 + j * 8 + (lane & 3) * 2;
            float b0 = bias[gc], b1 = bias[gc + 1];
            float v0 = acc[i][j][0] + b0, v1 = acc[i][j][1] + b1;
            float v2 = acc[i][j][2] + b0, v3 = acc[i][j][3] + b1;
            if (SPLIT) {
                uint32_t h, l;
                split2(v0, v1, h, l);
                *reinterpret_cast<uint32_t*>(Chi + (size_t)gr0 * N + gc) = h;
                *reinterpret_cast<uint32_t*>(Clo + (size_t)gr0 * N + gc) = l;
                split2(v2, v3, h, l);
                *reinterpret_cast<uint32_t*>(Chi + (size_t)gr1 * N + gc) = h;
                *reinterpret_cast<uint32_t*>(Clo + (size_t)gr1 * N + gc) = l;
            } else {
                *reinterpret_cast<float2*>(Cf + (size_t)gr0 * N + gc) = make_float2(v0, v1);
                *reinterpret_cast<float2*>(Cf + (size_t)gr1 * N + gc) = make_float2(v2, v3);
            }
        }
    }
}

__global__ __launch_bounds__(256, 1)
void gemm_mma3(Gemm3Args args, int M, int N, int K)
{
    extern __shared__ char dsm[];
    char* sb = (char*)(((uintptr_t)dsm + 1023) & ~(uintptr_t)1023);
    const int g = blockIdx.z;
    gemm_core<true>(args.Ah[g], args.Al[g], args.Wh[g], args.Wl[g], args.bias[g],
                    nullptr, args.Ch[g], args.Cl[g], M, N, K, sb, smem_u32(sb));
}

__global__ __launch_bounds__(256, 1)
void gemm_mma_f32(const __nv_bfloat16* Ahi, const __nv_bfloat16* Alo,
                  const __nv_bfloat16* Whi, const __nv_bfloat16* Wlo,
                  const float* bias, float* Cf, int M, int N, int K)
{
    extern __shared__ char dsm[];
    char* sb = (char*)(((uintptr_t)dsm + 1023) & ~(uintptr_t)1023);
    gemm_core<false>(Ahi, Alo, Whi, Wlo, bias, Cf, nullptr, nullptr, M, N, K, sb, smem_u32(sb));
}

// ---------------------------------------------------------------------------
// SMEM for flash
// ---------------------------------------------------------------------------
#define BUFSZ  32768u
#define OKLO   8192u
#define OVHI   16384u
#define OVLO   24576u
#define OMSK   65536u
#define SMEM_BYTES (66048u + 1024u)

// ---------------------------------------------------------------------------
// FA2 attention, mma.sync bf16 hi/lo, ldsm x4-batched. CTA = 128 q rows.
// ---------------------------------------------------------------------------
__global__ __launch_bounds__(256, 1)
void flash_mma(const __nv_bfloat16* __restrict__ Qhi, const __nv_bfloat16* __restrict__ Qlo,
               const __nv_bfloat16* __restrict__ Khi, const __nv_bfloat16* __restrict__ Klo,
               const __nv_bfloat16* __restrict__ Vhi, const __nv_bfloat16* __restrict__ Vlo,
               const int* __restrict__ mask,
               __nv_bfloat16* __restrict__ Chi, __nv_bfloat16* __restrict__ Clo)
{
    extern __shared__ char dsm[];
    char* sb = (char*)(((uintptr_t)dsm + 1023) & ~(uintptr_t)1023);
    const uint32_t sbase = smem_u32(sb);

    const int tid  = threadIdx.x;
    const int wid  = tid >> 5;
    const int lane = tid & 31;

    const int b  = blockIdx.y >> 3;
    const int h  = blockIdx.y & 7;
    const int q0 = blockIdx.x * 128;

    const size_t bh_off = (size_t)b * SEQ * DMODEL + h * DK;
    const __nv_bfloat16* Qbh = Qhi + bh_off + (size_t)q0 * DMODEL;
    const __nv_bfloat16* Qbl = Qlo + bh_off + (size_t)q0 * DMODEL;
    const __nv_bfloat16* Kbh = Khi + bh_off;
    const __nv_bfloat16* Kbl = Klo + bh_off;
    const __nv_bfloat16* Vbh = Vhi + bh_off;
    const __nv_bfloat16* Vbl = Vlo + bh_off;
    const int* mb = mask + (size_t)b * SEQ;

    // stage Q (128x64 hi/lo)
    {
        const int qrow = tid >> 1;
        const int qc0  = (tid & 1) * 4;
        const __nv_bfloat16* qh_src = Qbh + (size_t)qrow * DMODEL;
        const __nv_bfloat16* ql_src = Qbl + (size_t)qrow * DMODEL;
#pragma unroll
        for (int e = 0; e < 4; e++) {
            int ch = qc0 + e;
            uint32_t so = SWZ((uint32_t)qrow * 128u + (uint32_t)ch * 16u);
            cpa16(sbase + so,          qh_src + ch * 8);
            cpa16(sbase + 16384u + so, ql_src + ch * 8);
        }
        CP_COMMIT();
    }
    CP_WAIT(0);
    __syncthreads();

    uint32_t qh[4][4], ql[4][4];
    {
        const int r  = wid * 16 + (lane & 15);
        const int cb = (lane >> 4);
#pragma unroll
        for (int ks = 0; ks < 4; ks++) {
            uint32_t off = SWZ((uint32_t)r * 128u + (uint32_t)(ks * 2 + cb) * 16u);
            ldsm_x4(qh[ks], sbase + off);
            ldsm_x4(ql[ks], sbase + 16384u + off);
        }
    }
    __syncthreads();

    const int row = tid >> 2;
    const int ch0 = (tid & 3) * 2;

    {
        size_t ro = (size_t)row * DMODEL;
#pragma unroll
        for (int e = 0; e < 2; e++) {
            int ch = ch0 + e;
            uint32_t so = SWZ((uint32_t)row * 128u + (uint32_t)ch * 16u);
            cpa16(sbase + so,        Kbh + ro + ch * 8);
            cpa16(sbase + OKLO + so, Kbl + ro + ch * 8);
            cpa16(sbase + OVHI + so, Vbh + ro + ch * 8);
            cpa16(sbase + OVLO + so, Vbl + ro + ch * 8);
        }
        CP_COMMIT();
        if (tid < 64) ((float*)(sb + OMSK))[tid] = (mb[tid] == 0) ? -1e9f : 0.f;
    }

    float o[8][4];
#pragma unroll
    for (int nb = 0; nb < 8; nb++)
#pragma unroll
        for (int j = 0; j < 4; j++) o[nb][j] = 0.f;
    float m0 = -1e30f, m1 = -1e30f, l0 = 0.f, l1 = 0.f;

    // x4 address components
    const int k_row4 = ((lane >> 4) & 1) * 8 + (lane & 7);   // K frag rows within nb-pair
    const int k_ch4  = (lane >> 3) & 1;                      // chunk within k-step
    const int v_row4 = lane & 15;                            // V frag rows within k-step
    const int v_cb4  = (lane >> 4) & 1;                      // nb within pair

    const int nT = SEQ / 64;
    for (int t = 0; t < nT; t++) {
        const uint32_t p  = (uint32_t)(t & 1);
        const uint32_t bb = sbase + p * BUFSZ;
        float* mskp = (float*)(sb + OMSK + p * 256u);

        if (t + 1 < nT) {
            size_t ro = (size_t)((t + 1) * 64 + row) * DMODEL;
            uint32_t ob = sbase + (p ^ 1u) * BUFSZ;
#pragma unroll
            for (int e = 0; e < 2; e++) {
                int ch = ch0 + e;
                uint32_t so = SWZ((uint32_t)row * 128u + (uint32_t)ch * 16u);
                cpa16(ob + so,        Kbh + ro + ch * 8);
                cpa16(ob + OKLO + so, Kbl + ro + ch * 8);
                cpa16(ob + OVHI + so, Vbh + ro + ch * 8);
                cpa16(ob + OVLO + so, Vbl + ro + ch * 8);
            }
            if (tid < 64)
                ((float*)(sb + OMSK + (p ^ 1u) * 256u))[tid] =
                    (mb[(t + 1) * 64 + tid] == 0) ? -1e9f : 0.f;
        }
        CP_COMMIT();
        CP_WAIT(1);
        __syncthreads();

        // ---- S = Q K^T (x4-batched K loads: two nb per ldsm) ----
        float s[8][4];
#pragma unroll
        for (int nb = 0; nb < 8; nb++)
#pragma unroll
            for (int j = 0; j < 4; j++) s[nb][j] = 0.f;

#pragma unroll
        for (int nbp = 0; nbp < 4; nbp++) {
            const int krow = nbp * 16 + k_row4;
#pragma unroll
            for (int ks = 0; ks < 4; ks++) {
                uint32_t off = SWZ((uint32_t)krow * 128u + (uint32_t)(ks * 2 + k_ch4) * 16u);
                uint32_t kh4[4], kl4[4];
                ldsm_x4(kh4, bb + off);
                ldsm_x4(kl4, bb + OKLO + off);
                mma16816(s[2 * nbp],     qh[ks], kh4[0], kh4[1]);
                mma16816(s[2 * nbp],     ql[ks], kh4[0], kh4[1]);
                mma16816(s[2 * nbp],     qh[ks], kl4[0], kl4[1]);
                mma16816(s[2 * nbp + 1], qh[ks], kh4[2], kh4[3]);
                mma16816(s[2 * nbp + 1], ql[ks], kh4[2], kh4[3]);
                mma16816(s[2 * nbp + 1], qh[ks], kl4[2], kl4[3]);
            }
        }

        // ---- online softmax ----
        float rm0 = -1e30f, rm1 = -1e30f;
#pragma unroll
        for (int nb = 0; nb < 8; nb++) {
            float2 mk = *(const float2*)(mskp + nb * 8 + (lane & 3) * 2);
            s[nb][0] = s[nb][0] * 0.125f + mk.x;
            s[nb][1] = s[nb][1] * 0.125f + mk.y;
            s[nb][2] = s[nb][2] * 0.125f + mk.x;
            s[nb][3] = s[nb][3] * 0.125f + mk.y;
            rm0 = fmaxf(rm0, fmaxf(s[nb][0], s[nb][1]));
            rm1 = fmaxf(rm1, fmaxf(s[nb][2], s[nb][3]));
        }
        rm0 = fmaxf(rm0, __shfl_xor_sync(0xffffffffu, rm0, 1));
        rm0 = fmaxf(rm0, __shfl_xor_sync(0xffffffffu, rm0, 2));
        rm1 = fmaxf(rm1, __shfl_xor_sync(0xffffffffu, rm1, 1));
        rm1 = fmaxf(rm1, __shfl_xor_sync(0xffffffffu, rm1, 2));

        const float mn0 = fmaxf(m0, rm0), mn1 = fmaxf(m1, rm1);
        const float a0 = __expf(m0 - mn0), a1 = __expf(m1 - mn1);
        m0 = mn0; m1 = mn1;

        float rs0 = 0.f, rs1 = 0.f;
#pragma unroll
        for (int nb = 0; nb < 8; nb++) {
            s[nb][0] = __expf(s[nb][0] - mn0);
            s[nb][1] = __expf(s[nb][1] - mn0);
            s[nb][2] = __expf(s[nb][2] - mn1);
            s[nb][3] = __expf(s[nb][3] - mn1);
            rs0 += s[nb][0] + s[nb][1];
            rs1 += s[nb][2] + s[nb][3];
        }
        rs0 += __shfl_xor_sync(0xffffffffu, rs0, 1);
        rs0 += __shfl_xor_sync(0xffffffffu, rs0, 2);
        rs1 += __shfl_xor_sync(0xffffffffu, rs1, 1);
        rs1 += __shfl_xor_sync(0xffffffffu, rs1, 2);
        l0 = l0 * a0 + rs0;
        l1 = l1 * a1 + rs1;

#pragma unroll
        for (int nb = 0; nb < 8; nb++) {
            o[nb][0] *= a0; o[nb][1] *= a0;
            o[nb][2] *= a1; o[nb][3] *= a1;
        }

        uint32_t ph[8][2], pl[8][2];
#pragma unroll
        for (int nb = 0; nb < 8; nb++) {
            split2(s[nb][0], s[nb][1], ph[nb][0], pl[nb][0]);
            split2(s[nb][2], s[nb][3], ph[nb][1], pl[nb][1]);
        }

        // ---- O += P V (x4-trans-batched V loads: two nb per ldsm) ----
#pragma unroll
        for (int ks = 0; ks < 4; ks++) {
            const int vrow = ks * 16 + v_row4;
            uint32_t ah[4] = {ph[2 * ks][0], ph[2 * ks][1], ph[2 * ks + 1][0], ph[2 * ks + 1][1]};
            uint32_t al[4] = {pl[2 * ks][0], pl[2 * ks][1], pl[2 * ks + 1][0], pl[2 * ks + 1][1]};
#pragma unroll
            for (int nbp = 0; nbp < 4; nbp++) {
                uint32_t off = SWZ((uint32_t)vrow * 128u + (uint32_t)(nbp * 2 + v_cb4) * 16u);
                uint32_t vh4[4], vl4[4];
                ldsm_x4t(vh4, bb + OVHI + off);
                ldsm_x4t(vl4, bb + OVLO + off);
                mma16816(o[2 * nbp],     ah, vh4[0], vh4[1]);
                mma16816(o[2 * nbp],     al, vh4[0], vh4[1]);
                mma16816(o[2 * nbp],     ah, vl4[0], vl4[1]);
                mma16816(o[2 * nbp + 1], ah, vh4[2], vh4[3]);
                mma16816(o[2 * nbp + 1], al, vh4[2], vh4[3]);
                mma16816(o[2 * nbp + 1], ah, vl4[2], vl4[3]);
            }
        }
        __syncthreads();
    }

    // epilogue: write ctx hi/lo bf16
    const float i0 = 1.f / l0, i1 = 1.f / l1;
    const int r  = lane >> 2;
    const int cb = (lane & 3) * 2;
    const size_t ob0 = ((size_t)b * SEQ + q0 + wid * 16) * DMODEL + h * DK;
#pragma unroll
    for (int nb = 0; nb < 8; nb++) {
        uint32_t hh, ll;
        size_t off0 = ob0 + (size_t)r * DMODEL + nb * 8 + cb;
        split2(o[nb][0] * i0, o[nb][1] * i0, hh, ll);
        *reinterpret_cast<uint32_t*>(Chi + off0) = hh;
        *reinterpret_cast<uint32_t*>(Clo + off0) = ll;
        size_t off1 = ob0 + (size_t)(r + 8) * DMODEL + nb * 8 + cb;
        split2(o[nb][2] * i1, o[nb][3] * i1, hh, ll);
        *reinterpret_cast<uint32_t*>(Chi + off1) = hh;
        *reinterpret_cast<uint32_t*>(Clo + off1) = ll;
    }
}

// ---------------------------------------------------------------------------
extern "C" void kernel_launch(void* const* d_in, const int* in_sizes, int n_in,
                              void* d_out, int out_size)
{
    const float* q    = (const float*)d_in[0];
    const float* k    = (const float*)d_in[1];
    const float* v    = (const float*)d_in[2];
    const int*   mask = (const int*)  d_in[3];
    const float* Wq   = (const float*)d_in[4];
    const float* bq   = (const float*)d_in[5];
    const float* Wk   = (const float*)d_in[6];
    const float* bk   = (const float*)d_in[7];
    const float* Wv   = (const float*)d_in[8];
    const float* bv   = (const float*)d_in[9];
    const float* Wo   = (const float*)d_in[10];
    const float* bo   = (const float*)d_in[11];

    const int S = SEQ, D = DMODEL;
    const int B = in_sizes[0] / (S * D);
    const int M = B * S;

    __nv_bfloat16 *qin_h, *qin_l, *kin_h, *kin_l, *vin_h, *vin_l;
    __nv_bfloat16 *Qh, *Ql, *Kh, *Kl, *Vh, *Vl, *Ch, *Cl;
    __nv_bfloat16 *Wqh, *Wql, *Wkh, *Wkl, *Wvh, *Wvl, *Woh, *Wol;
    cudaGetSymbolAddress((void**)&qin_h, g_qin_h); cudaGetSymbolAddress((void**)&qin_l, g_qin_l);
    cudaGetSymbolAddress((void**)&kin_h, g_kin_h); cudaGetSymbolAddress((void**)&kin_l, g_kin_l);
    cudaGetSymbolAddress((void**)&vin_h, g_vin_h); cudaGetSymbolAddress((void**)&vin_l, g_vin_l);
    cudaGetSymbolAddress((void**)&Qh, g_Qhi); cudaGetSymbolAddress((void**)&Ql, g_Qlo);
    cudaGetSymbolAddress((void**)&Kh, g_Khi); cudaGetSymbolAddress((void**)&Kl, g_Klo);
    cudaGetSymbolAddress((void**)&Vh, g_Vhi); cudaGetSymbolAddress((void**)&Vl, g_Vlo);
    cudaGetSymbolAddress((void**)&Ch, g_Chi); cudaGetSymbolAddress((void**)&Cl, g_Clo);
    cudaGetSymbolAddress((void**)&Wqh, g_Wq_h); cudaGetSymbolAddress((void**)&Wql, g_Wq_l);
    cudaGetSymbolAddress((void**)&Wkh, g_Wk_h); cudaGetSymbolAddress((void**)&Wkl, g_Wk_l);
    cudaGetSymbolAddress((void**)&Wvh, g_Wv_h); cudaGetSymbolAddress((void**)&Wvl, g_Wv_l);
    cudaGetSymbolAddress((void**)&Woh, g_Wo_h); cudaGetSymbolAddress((void**)&Wol, g_Wo_l);

    // conversions: inputs (3-batched) + weights (4-batched)
    const int nIn4 = (M * D) / 4, nW4 = (D * D) / 4;
    {
        Conv4Args ca{};
        ca.X[0] = q; ca.hi[0] = qin_h; ca.lo[0] = qin_l;
        ca.X[1] = k; ca.hi[1] = kin_h; ca.lo[1] = kin_l;
        ca.X[2] = v; ca.hi[2] = vin_h; ca.lo[2] = vin_l;
        dim3 cg((nIn4 + 255) / 256, 1, 3);
        convert_split4<<<cg, 256>>>(ca, nIn4);
    }
    {
        Conv4Args ca{};
        ca.X[0] = Wq; ca.hi[0] = Wqh; ca.lo[0] = Wql;
        ca.X[1] = Wk; ca.hi[1] = Wkh; ca.lo[1] = Wkl;
        ca.X[2] = Wv; ca.hi[2] = Wvh; ca.lo[2] = Wvl;
        ca.X[3] = Wo; ca.hi[3] = Woh; ca.lo[3] = Wol;
        dim3 cg((nW4 + 255) / 256, 1, 4);
        convert_split4<<<cg, 256>>>(ca, nW4);
    }

    // Q/K/V projections: one batched launch
    cudaFuncSetAttribute(gemm_mma3,    cudaFuncAttributeMaxDynamicSharedMemorySize, GSMEM);
    cudaFuncSetAttribute(gemm_mma_f32, cudaFuncAttributeMaxDynamicSharedMemorySize, GSMEM);
    {
        Gemm3Args ga{};
        ga.Ah[0] = qin_h; ga.Al[0] = qin_l; ga.Wh[0] = Wqh; ga.Wl[0] = Wql; ga.bias[0] = bq; ga.Ch[0] = Qh; ga.Cl[0] = Ql;
        ga.Ah[1] = kin_h; ga.Al[1] = kin_l; ga.Wh[1] = Wkh; ga.Wl[1] = Wkl; ga.bias[1] = bk; ga.Ch[1] = Kh; ga.Cl[1] = Kl;
        ga.Ah[2] = vin_h; ga.Al[2] = vin_l; ga.Wh[2] = Wvh; ga.Wl[2] = Wvl; ga.bias[2] = bv; ga.Ch[2] = Vh; ga.Cl[2] = Vl;
        dim3 gg(D / 128, M / 128, 3);
        gemm_mma3<<<gg, 256, GSMEM>>>(ga, M, D, D);
    }

    // attention
    cudaFuncSetAttribute(flash_mma, cudaFuncAttributeMaxDynamicSharedMemorySize, SMEM_BYTES);
    flash_mma<<<dim3(S / 128, B * NHEAD), 256, SMEM_BYTES>>>(Qh, Ql, Kh, Kl, Vh, Vl, mask, Ch, Cl);

    // output projection (fp32 out)
    gemm_mma_f32<<<dim3(D / 128, M / 128), 256, GSMEM>>>(Ch, Cl, Woh, Wol, bo, (float*)d_out, M, D, D);
}

// round 8
// speedup vs baseline: 1.0378x; 1.0378x over previous
#include <cuda_runtime.h>
#include <cuda_bf16.h>
#include <cstdint>
#include <cstddef>

#define SEQ    4096
#define DMODEL 512
#define NHEAD  8
#define DK     64

// ---------------------------------------------------------------------------
// Scratch (device globals — no allocation in kernel_launch)
// ---------------------------------------------------------------------------
__device__ __nv_bfloat16 g_qin_h[2 * SEQ * DMODEL], g_qin_l[2 * SEQ * DMODEL];
__device__ __nv_bfloat16 g_kin_h[2 * SEQ * DMODEL], g_kin_l[2 * SEQ * DMODEL];
__device__ __nv_bfloat16 g_vin_h[2 * SEQ * DMODEL], g_vin_l[2 * SEQ * DMODEL];
__device__ __nv_bfloat16 g_Qhi[2 * SEQ * DMODEL], g_Qlo[2 * SEQ * DMODEL];
__device__ __nv_bfloat16 g_Khi[2 * SEQ * DMODEL], g_Klo[2 * SEQ * DMODEL];
__device__ __nv_bfloat16 g_Vhi[2 * SEQ * DMODEL], g_Vlo[2 * SEQ * DMODEL];
__device__ __nv_bfloat16 g_Chi[2 * SEQ * DMODEL], g_Clo[2 * SEQ * DMODEL];
__device__ __nv_bfloat16 g_Wq_h[DMODEL * DMODEL], g_Wq_l[DMODEL * DMODEL];
__device__ __nv_bfloat16 g_Wk_h[DMODEL * DMODEL], g_Wk_l[DMODEL * DMODEL];
__device__ __nv_bfloat16 g_Wv_h[DMODEL * DMODEL], g_Wv_l[DMODEL * DMODEL];
__device__ __nv_bfloat16 g_Wo_h[DMODEL * DMODEL], g_Wo_l[DMODEL * DMODEL];

// ---------------------------------------------------------------------------
// helpers
// ---------------------------------------------------------------------------
#define SWZ(o) ((o) ^ (((o) >> 3) & 0x70))

__device__ __forceinline__ uint32_t smem_u32(const void* p) {
    uint32_t a;
    asm("{ .reg .u64 t; cvta.to.shared.u64 t, %1; cvt.u32.u64 %0, t; }" : "=r"(a) : "l"(p));
    return a;
}
__device__ __forceinline__ void cpa16(uint32_t dst, const void* src) {
    asm volatile("cp.async.cg.shared.global [%0], [%1], 16;" :: "r"(dst), "l"(src) : "memory");
}
#define CP_COMMIT() asm volatile("cp.async.commit_group;" ::: "memory")
#define CP_WAIT(n)  asm volatile("cp.async.wait_group %0;" :: "n"(n) : "memory")

__device__ __forceinline__ void ldsm_x4(uint32_t* r, uint32_t addr) {
    asm volatile("ldmatrix.sync.aligned.m8n8.x4.shared.b16 {%0,%1,%2,%3}, [%4];"
                 : "=r"(r[0]), "=r"(r[1]), "=r"(r[2]), "=r"(r[3]) : "r"(addr));
}
__device__ __forceinline__ void ldsm_x4t(uint32_t* r, uint32_t addr) {
    asm volatile("ldmatrix.sync.aligned.m8n8.x4.trans.shared.b16 {%0,%1,%2,%3}, [%4];"
                 : "=r"(r[0]), "=r"(r[1]), "=r"(r[2]), "=r"(r[3]) : "r"(addr));
}
__device__ __forceinline__ void mma16816(float* c, const uint32_t* a, uint32_t b0, uint32_t b1) {
    asm volatile("mma.sync.aligned.m16n8k16.row.col.f32.bf16.bf16.f32 "
                 "{%0,%1,%2,%3}, {%4,%5,%6,%7}, {%8,%9}, {%0,%1,%2,%3};"
                 : "+f"(c[0]), "+f"(c[1]), "+f"(c[2]), "+f"(c[3])
                 : "r"(a[0]), "r"(a[1]), "r"(a[2]), "r"(a[3]), "r"(b0), "r"(b1));
}
__device__ __forceinline__ void split2(float a, float b, uint32_t& hi, uint32_t& lo) {
    __nv_bfloat162 hp = __floats2bfloat162_rn(a, b);
    float ar = a - __bfloat162float(hp.x);
    float br = b - __bfloat162float(hp.y);
    __nv_bfloat162 lp = __floats2bfloat162_rn(ar, br);
    hi = *reinterpret_cast<uint32_t*>(&hp);
    lo = *reinterpret_cast<uint32_t*>(&lp);
}
__device__ __forceinline__ float ex2f(float x) {
    float y;
    asm("ex2.approx.f32 %0, %1;" : "=f"(y) : "f"(x));
    return y;
}

// scale in log2 domain: 1/sqrt(64) * log2(e)
#define SCALE2   0.1803368801111204f
#define MASKNEG -1.4426950408889634e9f

// ---------------------------------------------------------------------------
// batched elementwise fp32 -> bf16 hi/lo
// ---------------------------------------------------------------------------
struct Conv4Args {
    const float* X[4];
    __nv_bfloat16* hi[4];
    __nv_bfloat16* lo[4];
};

__global__ __launch_bounds__(256)
void convert_split4(Conv4Args args, int n4)
{
    const int g = blockIdx.z;
    int i = blockIdx.x * blockDim.x + threadIdx.x;
    if (i >= n4) return;
    float4 v = *reinterpret_cast<const float4*>(args.X[g] + (size_t)i * 4);
    uint32_t h0, l0, h1, l1;
    split2(v.x, v.y, h0, l0);
    split2(v.z, v.w, h1, l1);
    *reinterpret_cast<uint2*>(args.hi[g] + (size_t)i * 4) = make_uint2(h0, h1);
    *reinterpret_cast<uint2*>(args.lo[g] + (size_t)i * 4) = make_uint2(l0, l1);
}

// ---------------------------------------------------------------------------
// Tensor-core GEMM core (128x128 tile, K-step 64, 8 warps, double-buffered)
// ---------------------------------------------------------------------------
#define GA_HI 0u
#define GA_LO 16384u
#define GW_HI 32768u
#define GW_LO 49152u
#define GBUF  65536u
#define GSMEM (131072u + 1024u)

struct Gemm3Args {
    const __nv_bfloat16* Ah[3];
    const __nv_bfloat16* Al[3];
    const __nv_bfloat16* Wh[3];
    const __nv_bfloat16* Wl[3];
    const float* bias[3];
    __nv_bfloat16* Ch[3];
    __nv_bfloat16* Cl[3];
};

template<bool SPLIT>
__device__ __forceinline__ void gemm_core(
    const __nv_bfloat16* __restrict__ Ahi, const __nv_bfloat16* __restrict__ Alo,
    const __nv_bfloat16* __restrict__ Whi, const __nv_bfloat16* __restrict__ Wlo,
    const float* __restrict__ bias, float* __restrict__ Cf,
    __nv_bfloat16* __restrict__ Chi, __nv_bfloat16* __restrict__ Clo,
    int M, int N, int K, char* sb, uint32_t sbase)
{
    const int tid  = threadIdx.x;
    const int wid  = tid >> 5;
    const int lane = tid & 31;
    const int wm   = wid & 1;
    const int wn   = wid >> 1;

    const int brow = blockIdx.y * 128;
    const int bcol = blockIdx.x * 128;

    const int row = tid >> 1;
    const int ch0 = (tid & 1) * 4;

    const __nv_bfloat16* a_h = Ahi + (size_t)(brow + row) * K;
    const __nv_bfloat16* a_l = Alo + (size_t)(brow + row) * K;
    const __nv_bfloat16* w_h = Whi + (size_t)(bcol + row) * K;
    const __nv_bfloat16* w_l = Wlo + (size_t)(bcol + row) * K;
    const uint32_t so_base = (uint32_t)row * 128u;

    {
#pragma unroll
        for (int e = 0; e < 4; e++) {
            int ch = ch0 + e;
            uint32_t so = SWZ(so_base + (uint32_t)ch * 16u);
            cpa16(sbase + GA_HI + so, a_h + ch * 8);
            cpa16(sbase + GA_LO + so, a_l + ch * 8);
            cpa16(sbase + GW_HI + so, w_h + ch * 8);
            cpa16(sbase + GW_LO + so, w_l + ch * 8);
        }
        CP_COMMIT();
    }

    float acc[4][4][4];
#pragma unroll
    for (int i = 0; i < 4; i++)
#pragma unroll
        for (int j = 0; j < 4; j++)
#pragma unroll
            for (int e = 0; e < 4; e++) acc[i][j][e] = 0.f;

    const int nKT = K / 64;
    for (int kt = 0; kt < nKT; kt++) {
        const uint32_t p  = (uint32_t)(kt & 1);
        const uint32_t bb = sbase + p * GBUF;

        if (kt + 1 < nKT) {
            const int k1 = (kt + 1) * 64;
            uint32_t ob = sbase + (p ^ 1u) * GBUF;
#pragma unroll
            for (int e = 0; e < 4; e++) {
                int ch = ch0 + e;
                uint32_t so = SWZ(so_base + (uint32_t)ch * 16u);
                cpa16(ob + GA_HI + so, a_h + k1 + ch * 8);
                cpa16(ob + GA_LO + so, a_l + k1 + ch * 8);
                cpa16(ob + GW_HI + so, w_h + k1 + ch * 8);
                cpa16(ob + GW_LO + so, w_l + k1 + ch * 8);
            }
        }
        CP_COMMIT();
        CP_WAIT(1);
        __syncthreads();

#pragma unroll
        for (int ks = 0; ks < 4; ks++) {
            uint32_t ah[4][4], al[4][4];
            const int cb = lane >> 4;
#pragma unroll
            for (int i = 0; i < 4; i++) {
                int r = wm * 64 + i * 16 + (lane & 15);
                uint32_t off = SWZ((uint32_t)r * 128u + (uint32_t)(ks * 2 + cb) * 16u);
                ldsm_x4(ah[i], bb + GA_HI + off);
                ldsm_x4(al[i], bb + GA_LO + off);
            }
            uint32_t bh[4][2], bl[4][2];
#pragma unroll
            for (int jp = 0; jp < 2; jp++) {
                int wr = wn * 32 + (jp * 2 + (lane >> 4)) * 8 + (lane & 7);
                int ch = ks * 2 + ((lane >> 3) & 1);
                uint32_t off = SWZ((uint32_t)wr * 128u + (uint32_t)ch * 16u);
                uint32_t t4[4];
                ldsm_x4(t4, bb + GW_HI + off);
                bh[jp * 2][0] = t4[0]; bh[jp * 2][1] = t4[1];
                bh[jp * 2 + 1][0] = t4[2]; bh[jp * 2 + 1][1] = t4[3];
                ldsm_x4(t4, bb + GW_LO + off);
                bl[jp * 2][0] = t4[0]; bl[jp * 2][1] = t4[1];
                bl[jp * 2 + 1][0] = t4[2]; bl[jp * 2 + 1][1] = t4[3];
            }
#pragma unroll
            for (int i = 0; i < 4; i++)
#pragma unroll
                for (int j = 0; j < 4; j++) {
                    mma16816(acc[i][j], ah[i], bh[j][0], bh[j][1]);
                    mma16816(acc[i][j], al[i], bh[j][0], bh[j][1]);
                    mma16816(acc[i][j], ah[i], bl[j][0], bl[j][1]);
                }
        }
        __syncthreads();
    }

#pragma unroll
    for (int i = 0; i < 4; i++) {
        const int gr0 = brow + wm * 64 + i * 16 + (lane >> 2);
        const int gr1 = gr0 + 8;
#pragma unroll
        for (int j = 0; j < 4; j++) {
            const int gc = bcol + wn * 32 + j * 8 + (lane & 3) * 2;
            float b0 = bias[gc], b1 = bias[gc + 1];
            float v0 = acc[i][j][0] + b0, v1 = acc[i][j][1] + b1;
            float v2 = acc[i][j][2] + b0, v3 = acc[i][j][3] + b1;
            if (SPLIT) {
                uint32_t h, l;
                split2(v0, v1, h, l);
                *reinterpret_cast<uint32_t*>(Chi + (size_t)gr0 * N + gc) = h;
                *reinterpret_cast<uint32_t*>(Clo + (size_t)gr0 * N + gc) = l;
                split2(v2, v3, h, l);
                *reinterpret_cast<uint32_t*>(Chi + (size_t)gr1 * N + gc) = h;
                *reinterpret_cast<uint32_t*>(Clo + (size_t)gr1 * N + gc) = l;
            } else {
                *reinterpret_cast<float2*>(Cf + (size_t)gr0 * N + gc) = make_float2(v0, v1);
                *reinterpret_cast<float2*>(Cf + (size_t)gr1 * N + gc) = make_float2(v2, v3);
            }
        }
    }
}

__global__ __launch_bounds__(256, 1)
void gemm_mma3(Gemm3Args args, int M, int N, int K)
{
    extern __shared__ char dsm[];
    char* sb = (char*)(((uintptr_t)dsm + 1023) & ~(uintptr_t)1023);
    const int g = blockIdx.z;
    gemm_core<true>(args.Ah[g], args.Al[g], args.Wh[g], args.Wl[g], args.bias[g],
                    nullptr, args.Ch[g], args.Cl[g], M, N, K, sb, smem_u32(sb));
}

__global__ __launch_bounds__(256, 1)
void gemm_mma_f32(const __nv_bfloat16* Ahi, const __nv_bfloat16* Alo,
                  const __nv_bfloat16* Whi, const __nv_bfloat16* Wlo,
                  const float* bias, float* Cf, int M, int N, int K)
{
    extern __shared__ char dsm[];
    char* sb = (char*)(((uintptr_t)dsm + 1023) & ~(uintptr_t)1023);
    gemm_core<false>(Ahi, Alo, Whi, Wlo, bias, Cf, nullptr, nullptr, M, N, K, sb, smem_u32(sb));
}

// ---------------------------------------------------------------------------
// SMEM for flash: 3-stage K/V ring (32KB each) + 3 mask slots.
// Q staging (hi 16KB @0, lo 16KB @16384) uses ring buffers 0+1 pre-loop.
// ---------------------------------------------------------------------------
#define BUFSZ  32768u
#define OKLO   8192u
#define OVHI   16384u
#define OVLO   24576u
#define OMSK   98304u
#define SMEM_BYTES (98304u + 768u + 1024u)

// ---------------------------------------------------------------------------
// FA2 attention, software-pipelined: QK(t+1) issued before softmax(t)/PV(t).
// CTA = 128 q rows (8 warps), 256 threads, 3-stage cp.async ring.
// ---------------------------------------------------------------------------
__global__ __launch_bounds__(256, 1)
void flash_mma(const __nv_bfloat16* __restrict__ Qhi, const __nv_bfloat16* __restrict__ Qlo,
               const __nv_bfloat16* __restrict__ Khi, const __nv_bfloat16* __restrict__ Klo,
               const __nv_bfloat16* __restrict__ Vhi, const __nv_bfloat16* __restrict__ Vlo,
               const int* __restrict__ mask,
               __nv_bfloat16* __restrict__ Chi, __nv_bfloat16* __restrict__ Clo)
{
    extern __shared__ char dsm[];
    char* sb = (char*)(((uintptr_t)dsm + 1023) & ~(uintptr_t)1023);
    const uint32_t sbase = smem_u32(sb);

    const int tid  = threadIdx.x;
    const int wid  = tid >> 5;
    const int lane = tid & 31;

    const int b  = blockIdx.y >> 3;
    const int h  = blockIdx.y & 7;
    const int q0 = blockIdx.x * 128;

    const size_t bh_off = (size_t)b * SEQ * DMODEL + h * DK;
    const __nv_bfloat16* Qbh = Qhi + bh_off + (size_t)q0 * DMODEL;
    const __nv_bfloat16* Qbl = Qlo + bh_off + (size_t)q0 * DMODEL;
    const __nv_bfloat16* Kbh = Khi + bh_off;
    const __nv_bfloat16* Kbl = Klo + bh_off;
    const __nv_bfloat16* Vbh = Vhi + bh_off;
    const __nv_bfloat16* Vbl = Vlo + bh_off;
    const int* mb = mask + (size_t)b * SEQ;

    // ---- stage Q (128x64 hi/lo) via cp.async into ring area ----
    {
        const int qrow = tid >> 1;
        const int qc0  = (tid & 1) * 4;
        const __nv_bfloat16* qh_src = Qbh + (size_t)qrow * DMODEL;
        const __nv_bfloat16* ql_src = Qbl + (size_t)qrow * DMODEL;
#pragma unroll
        for (int e = 0; e < 4; e++) {
            int ch = qc0 + e;
            uint32_t so = SWZ((uint32_t)qrow * 128u + (uint32_t)ch * 16u);
            cpa16(sbase + so,          qh_src + ch * 8);
            cpa16(sbase + 16384u + so, ql_src + ch * 8);
        }
        CP_COMMIT();
    }
    CP_WAIT(0);
    __syncthreads();

    uint32_t qh[4][4], ql[4][4];
    {
        const int r  = wid * 16 + (lane & 15);
        const int cb = (lane >> 4);
#pragma unroll
        for (int ks = 0; ks < 4; ks++) {
            uint32_t off = SWZ((uint32_t)r * 128u + (uint32_t)(ks * 2 + cb) * 16u);
            ldsm_x4(qh[ks], sbase + off);
            ldsm_x4(ql[ks], sbase + 16384u + off);
        }
    }
    __syncthreads();   // Q staging consumed before tile 0/1 loads overwrite

    const int row = tid >> 2;
    const int ch0 = (tid & 3) * 2;

    auto prefetch = [&](int tile, int buf) {
        size_t ro = (size_t)(tile * 64 + row) * DMODEL;
        uint32_t ob = sbase + (uint32_t)buf * BUFSZ;
#pragma unroll
        for (int e = 0; e < 2; e++) {
            int ch = ch0 + e;
            uint32_t so = SWZ((uint32_t)row * 128u + (uint32_t)ch * 16u);
            cpa16(ob + so,        Kbh + ro + ch * 8);
            cpa16(ob + OKLO + so, Kbl + ro + ch * 8);
            cpa16(ob + OVHI + so, Vbh + ro + ch * 8);
            cpa16(ob + OVLO + so, Vbl + ro + ch * 8);
        }
        if (tid < 64)
            ((float*)(sb + OMSK + (uint32_t)buf * 256u))[tid] =
                (mb[tile * 64 + tid] == 0) ? MASKNEG : 0.f;
        CP_COMMIT();
    };

    // x4 address components
    const int k_row4 = ((lane >> 4) & 1) * 8 + (lane & 7);
    const int k_ch4  = (lane >> 3) & 1;
    const int v_row4 = lane & 15;
    const int v_cb4  = (lane >> 4) & 1;

    auto qk_tile = [&](uint32_t bb, float (*s)[4]) {
#pragma unroll
        for (int nb = 0; nb < 8; nb++)
#pragma unroll
            for (int j = 0; j < 4; j++) s[nb][j] = 0.f;
#pragma unroll
        for (int nbp = 0; nbp < 4; nbp++) {
            const int krow = nbp * 16 + k_row4;
#pragma unroll
            for (int ks = 0; ks < 4; ks++) {
                uint32_t off = SWZ((uint32_t)krow * 128u + (uint32_t)(ks * 2 + k_ch4) * 16u);
                uint32_t kh4[4], kl4[4];
                ldsm_x4(kh4, bb + off);
                ldsm_x4(kl4, bb + OKLO + off);
                // pair-interleaved: same-accumulator distance 2
                mma16816(s[2 * nbp],     qh[ks], kh4[0], kh4[1]);
                mma16816(s[2 * nbp + 1], qh[ks], kh4[2], kh4[3]);
                mma16816(s[2 * nbp],     ql[ks], kh4[0], kh4[1]);
                mma16816(s[2 * nbp + 1], ql[ks], kh4[2], kh4[3]);
                mma16816(s[2 * nbp],     qh[ks], kl4[0], kl4[1]);
                mma16816(s[2 * nbp + 1], qh[ks], kl4[2], kl4[3]);
            }
        }
    };

    // ---- prologue: tiles 0 and 1 in flight, QK(0) computed ----
    prefetch(0, 0);
    prefetch(1, 1);

    float s_cur[8][4], s_nxt[8][4];
    CP_WAIT(1);          // tile 0 complete
    __syncthreads();
    qk_tile(sbase, s_cur);

    float o[8][4];
#pragma unroll
    for (int nb = 0; nb < 8; nb++)
#pragma unroll
        for (int j = 0; j < 4; j++) o[nb][j] = 0.f;
    float m0 = -1e30f, m1 = -1e30f, l0 = 0.f, l1 = 0.f;

    int b0 = 0, b1 = 1, b2 = 2;
    const int nT = SEQ / 64;
    for (int t = 0; t < nT; t++) {
        CP_WAIT(0);          // tiles <= t+1 arrived
        __syncthreads();     // all warps done with buffer b2 (PV(t-1)); data visible
        if (t + 2 < nT) prefetch(t + 2, b2);

        // ---- QK(t+1): independent tensor work to overlap with softmax(t) ----
        if (t + 1 < nT) qk_tile(sbase + (uint32_t)b1 * BUFSZ, s_nxt);

        float* mskp = (float*)(sb + OMSK + (uint32_t)b0 * 256u);

        // ---- online softmax on s_cur (log2 domain) ----
        float rm0 = -1e30f, rm1 = -1e30f;
#pragma unroll
        for (int nb = 0; nb < 8; nb++) {
            float2 mk = *(const float2*)(mskp + nb * 8 + (lane & 3) * 2);
            s_cur[nb][0] = s_cur[nb][0] * SCALE2 + mk.x;
            s_cur[nb][1] = s_cur[nb][1] * SCALE2 + mk.y;
            s_cur[nb][2] = s_cur[nb][2] * SCALE2 + mk.x;
            s_cur[nb][3] = s_cur[nb][3] * SCALE2 + mk.y;
            rm0 = fmaxf(rm0, fmaxf(s_cur[nb][0], s_cur[nb][1]));
            rm1 = fmaxf(rm1, fmaxf(s_cur[nb][2], s_cur[nb][3]));
        }
        rm0 = fmaxf(rm0, __shfl_xor_sync(0xffffffffu, rm0, 1));
        rm0 = fmaxf(rm0, __shfl_xor_sync(0xffffffffu, rm0, 2));
        rm1 = fmaxf(rm1, __shfl_xor_sync(0xffffffffu, rm1, 1));
        rm1 = fmaxf(rm1, __shfl_xor_sync(0xffffffffu, rm1, 2));

        const float mn0 = fmaxf(m0, rm0), mn1 = fmaxf(m1, rm1);
        const float a0 = ex2f(m0 - mn0), a1 = ex2f(m1 - mn1);
        m0 = mn0; m1 = mn1;

        float rs0 = 0.f, rs1 = 0.f;
#pragma unroll
        for (int nb = 0; nb < 8; nb++) {
            s_cur[nb][0] = ex2f(s_cur[nb][0] - mn0);
            s_cur[nb][1] = ex2f(s_cur[nb][1] - mn0);
            s_cur[nb][2] = ex2f(s_cur[nb][2] - mn1);
            s_cur[nb][3] = ex2f(s_cur[nb][3] - mn1);
            rs0 += s_cur[nb][0] + s_cur[nb][1];
            rs1 += s_cur[nb][2] + s_cur[nb][3];
        }
        rs0 += __shfl_xor_sync(0xffffffffu, rs0, 1);
        rs0 += __shfl_xor_sync(0xffffffffu, rs0, 2);
        rs1 += __shfl_xor_sync(0xffffffffu, rs1, 1);
        rs1 += __shfl_xor_sync(0xffffffffu, rs1, 2);
        l0 = l0 * a0 + rs0;
        l1 = l1 * a1 + rs1;

#pragma unroll
        for (int nb = 0; nb < 8; nb++) {
            o[nb][0] *= a0; o[nb][1] *= a0;
            o[nb][2] *= a1; o[nb][3] *= a1;
        }

        uint32_t ph[8][2], pl[8][2];
#pragma unroll
        for (int nb = 0; nb < 8; nb++) {
            split2(s_cur[nb][0], s_cur[nb][1], ph[nb][0], pl[nb][0]);
            split2(s_cur[nb][2], s_cur[nb][3], ph[nb][1], pl[nb][1]);
        }

        // ---- O += P V (buffer b0) ----
        {
            const uint32_t bb = sbase + (uint32_t)b0 * BUFSZ;
#pragma unroll
            for (int ks = 0; ks < 4; ks++) {
                const int vrow = ks * 16 + v_row4;
                uint32_t ah[4] = {ph[2 * ks][0], ph[2 * ks][1], ph[2 * ks + 1][0], ph[2 * ks + 1][1]};
                uint32_t al[4] = {pl[2 * ks][0], pl[2 * ks][1], pl[2 * ks + 1][0], pl[2 * ks + 1][1]};
#pragma unroll
                for (int nbp = 0; nbp < 4; nbp++) {
                    uint32_t off = SWZ((uint32_t)vrow * 128u + (uint32_t)(nbp * 2 + v_cb4) * 16u);
                    uint32_t vh4[4], vl4[4];
                    ldsm_x4t(vh4, bb + OVHI + off);
                    ldsm_x4t(vl4, bb + OVLO + off);
                    mma16816(o[2 * nbp],     ah, vh4[0], vh4[1]);
                    mma16816(o[2 * nbp + 1], ah, vh4[2], vh4[3]);
                    mma16816(o[2 * nbp],     al, vh4[0], vh4[1]);
                    mma16816(o[2 * nbp + 1], al, vh4[2], vh4[3]);
                    mma16816(o[2 * nbp],     ah, vl4[0], vl4[1]);
                    mma16816(o[2 * nbp + 1], ah, vl4[2], vl4[3]);
                }
            }
        }

        // ---- rotate pipeline state ----
        if (t + 1 < nT) {
#pragma unroll
            for (int nb = 0; nb < 8; nb++)
#pragma unroll
                for (int j = 0; j < 4; j++) s_cur[nb][j] = s_nxt[nb][j];
        }
        int tb = b0; b0 = b1; b1 = b2; b2 = tb;
    }

    // ---- epilogue: write ctx hi/lo bf16 ----
    const float i0 = 1.f / l0, i1 = 1.f / l1;
    const int r  = lane >> 2;
    const int cb = (lane & 3) * 2;
    const size_t ob0 = ((size_t)b * SEQ + q0 + wid * 16) * DMODEL + h * DK;
#pragma unroll
    for (int nb = 0; nb < 8; nb++) {
        uint32_t hh, ll;
        size_t off0 = ob0 + (size_t)r * DMODEL + nb * 8 + cb;
        split2(o[nb][0] * i0, o[nb][1] * i0, hh, ll);
        *reinterpret_cast<uint32_t*>(Chi + off0) = hh;
        *reinterpret_cast<uint32_t*>(Clo + off0) = ll;
        size_t off1 = ob0 + (size_t)(r + 8) * DMODEL + nb * 8 + cb;
        split2(o[nb][2] * i1, o[nb][3] * i1, hh, ll);
        *reinterpret_cast<uint32_t*>(Chi + off1) = hh;
        *reinterpret_cast<uint32_t*>(Clo + off1) = ll;
    }
}

// ---------------------------------------------------------------------------
extern "C" void kernel_launch(void* const* d_in, const int* in_sizes, int n_in,
                              void* d_out, int out_size)
{
    const float* q    = (const float*)d_in[0];
    const float* k    = (const float*)d_in[1];
    const float* v    = (const float*)d_in[2];
    const int*   mask = (const int*)  d_in[3];
    const float* Wq   = (const float*)d_in[4];
    const float* bq   = (const float*)d_in[5];
    const float* Wk   = (const float*)d_in[6];
    const float* bk   = (const float*)d_in[7];
    const float* Wv   = (const float*)d_in[8];
    const float* bv   = (const float*)d_in[9];
    const float* Wo   = (const float*)d_in[10];
    const float* bo   = (const float*)d_in[11];

    const int S = SEQ, D = DMODEL;
    const int B = in_sizes[0] / (S * D);
    const int M = B * S;

    __nv_bfloat16 *qin_h, *qin_l, *kin_h, *kin_l, *vin_h, *vin_l;
    __nv_bfloat16 *Qh, *Ql, *Kh, *Kl, *Vh, *Vl, *Ch, *Cl;
    __nv_bfloat16 *Wqh, *Wql, *Wkh, *Wkl, *Wvh, *Wvl, *Woh, *Wol;
    cudaGetSymbolAddress((void**)&qin_h, g_qin_h); cudaGetSymbolAddress((void**)&qin_l, g_qin_l);
    cudaGetSymbolAddress((void**)&kin_h, g_kin_h); cudaGetSymbolAddress((void**)&kin_l, g_kin_l);
    cudaGetSymbolAddress((void**)&vin_h, g_vin_h); cudaGetSymbolAddress((void**)&vin_l, g_vin_l);
    cudaGetSymbolAddress((void**)&Qh, g_Qhi); cudaGetSymbolAddress((void**)&Ql, g_Qlo);
    cudaGetSymbolAddress((void**)&Kh, g_Khi); cudaGetSymbolAddress((void**)&Kl, g_Klo);
    cudaGetSymbolAddress((void**)&Vh, g_Vhi); cudaGetSymbolAddress((void**)&Vl, g_Vlo);
    cudaGetSymbolAddress((void**)&Ch, g_Chi); cudaGetSymbolAddress((void**)&Cl, g_Clo);
    cudaGetSymbolAddress((void**)&Wqh, g_Wq_h); cudaGetSymbolAddress((void**)&Wql, g_Wq_l);
    cudaGetSymbolAddress((void**)&Wkh, g_Wk_h); cudaGetSymbolAddress((void**)&Wkl, g_Wk_l);
    cudaGetSymbolAddress((void**)&Wvh, g_Wv_h); cudaGetSymbolAddress((void**)&Wvl, g_Wv_l);
    cudaGetSymbolAddress((void**)&Woh, g_Wo_h); cudaGetSymbolAddress((void**)&Wol, g_Wo_l);

    const int nIn4 = (M * D) / 4, nW4 = (D * D) / 4;
    {
        Conv4Args ca{};
        ca.X[0] = q; ca.hi[0] = qin_h; ca.lo[0] = qin_l;
        ca.X[1] = k; ca.hi[1] = kin_h; ca.lo[1] = kin_l;
        ca.X[2] = v; ca.hi[2] = vin_h; ca.lo[2] = vin_l;
        dim3 cg((nIn4 + 255) / 256, 1, 3);
        convert_split4<<<cg, 256>>>(ca, nIn4);
    }
    {
        Conv4Args ca{};
        ca.X[0] = Wq; ca.hi[0] = Wqh; ca.lo[0] = Wql;
        ca.X[1] = Wk; ca.hi[1] = Wkh; ca.lo[1] = Wkl;
        ca.X[2] = Wv; ca.hi[2] = Wvh; ca.lo[2] = Wvl;
        ca.X[3] = Wo; ca.hi[3] = Woh; ca.lo[3] = Wol;
        dim3 cg((nW4 + 255) / 256, 1, 4);
        convert_split4<<<cg, 256>>>(ca, nW4);
    }

    cudaFuncSetAttribute(gemm_mma3,    cudaFuncAttributeMaxDynamicSharedMemorySize, GSMEM);
    cudaFuncSetAttribute(gemm_mma_f32, cudaFuncAttributeMaxDynamicSharedMemorySize, GSMEM);
    {
        Gemm3Args ga{};
        ga.Ah[0] = qin_h; ga.Al[0] = qin_l; ga.Wh[0] = Wqh; ga.Wl[0] = Wql; ga.bias[0] = bq; ga.Ch[0] = Qh; ga.Cl[0] = Ql;
        ga.Ah[1] = kin_h; ga.Al[1] = kin_l; ga.Wh[1] = Wkh; ga.Wl[1] = Wkl; ga.bias[1] = bk; ga.Ch[1] = Kh; ga.Cl[1] = Kl;
        ga.Ah[2] = vin_h; ga.Al[2] = vin_l; ga.Wh[2] = Wvh; ga.Wl[2] = Wvl; ga.bias[2] = bv; ga.Ch[2] = Vh; ga.Cl[2] = Vl;
        dim3 gg(D / 128, M / 128, 3);
        gemm_mma3<<<gg, 256, GSMEM>>>(ga, M, D, D);
    }

    cudaFuncSetAttribute(flash_mma, cudaFuncAttributeMaxDynamicSharedMemorySize, SMEM_BYTES);
    flash_mma<<<dim3(S / 128, B * NHEAD), 256, SMEM_BYTES>>>(Qh, Ql, Kh, Kl, Vh, Vl, mask, Ch, Cl);

    gemm_mma_f32<<<dim3(D / 128, M / 128), 256, GSMEM>>>(Ch, Cl, Woh, Wol, bo, (float*)d_out, M, D, D);
}